// round 2
// baseline (speedup 1.0000x reference)
#include <cuda_runtime.h>
#include <cuda_bf16.h>
#include <math.h>

#define BB 64
#define TT 256
#define DD 1024
#define HH 8
#define DKk 128
#define GH 256
#define G3 768
#define MROWS (BB*TT)   // 16384

// ---------------- scratch (device globals; allocation is forbidden) --------
__device__ float g_X [MROWS*DD];
__device__ float g_Q [MROWS*DD];
__device__ float g_K [MROWS*DD];
__device__ float g_V [MROWS*DD];
__device__ float g_AO[MROWS*DD];
__device__ float g_GF[MROWS*G3];
__device__ float g_GB[MROWS*G3];
__device__ float g_H [2*2*BB*GH];   // [dir][parity][b][GH]
__device__ unsigned g_bar;

// ---------------------------------------------------------------------------
// init: zero output, zero h parity-0, reset barrier
// ---------------------------------------------------------------------------
__global__ void init_kernel(float* out, int out_n) {
    int i = blockIdx.x * blockDim.x + threadIdx.x;
    int stride = gridDim.x * blockDim.x;
    for (int k = i; k < out_n; k += stride) out[k] = 0.0f;
    // zero parity-0 h for both directions: [dir][0][b][GH]
    for (int k = i; k < BB*GH; k += stride) {
        g_H[(0*2+0)*BB*GH + k] = 0.0f;
        g_H[(1*2+0)*BB*GH + k] = 0.0f;
    }
    if (i == 0) g_bar = 0u;
}

// ---------------------------------------------------------------------------
// SGEMM: C[M,N] = A[M,K] @ W[N,K]^T + bias[N] (+ res[M,N])
// BM=BN=128, BK=8, 256 threads, 8x8 microtile (split-4 fragments)
// ---------------------------------------------------------------------------
#define BM 128
#define BN 128
#define BK 8

__global__ __launch_bounds__(256, 2)
void sgemm_bias(const float* __restrict__ A, const float* __restrict__ W,
                const float* __restrict__ bias, const float* __restrict__ res,
                float* __restrict__ C, int N, int K) {
    __shared__ float As[2][BK][BM];
    __shared__ float Bs[2][BK][BN];

    const int tid = threadIdx.x;
    const int bm = blockIdx.y * BM;
    const int bn = blockIdx.x * BN;

    const int lr = tid >> 1;          // 0..127 (row within tile)
    const int lk = (tid & 1) << 2;    // 0 or 4

    const float* Aptr = A + (bm + lr) * K + lk;
    const float* Wptr = W + (bn + lr) * K + lk;

    const int tx = tid & 15;          // 0..15
    const int ty = tid >> 4;          // 0..15

    float acc[8][8];
    #pragma unroll
    for (int i = 0; i < 8; i++)
        #pragma unroll
        for (int j = 0; j < 8; j++) acc[i][j] = 0.0f;

    // prologue: tile 0
    float4 a4 = *(const float4*)Aptr;
    float4 b4 = *(const float4*)Wptr;
    As[0][lk+0][lr] = a4.x; As[0][lk+1][lr] = a4.y;
    As[0][lk+2][lr] = a4.z; As[0][lk+3][lr] = a4.w;
    Bs[0][lk+0][lr] = b4.x; Bs[0][lk+1][lr] = b4.y;
    Bs[0][lk+2][lr] = b4.z; Bs[0][lk+3][lr] = b4.w;
    __syncthreads();

    const int nk = K / BK;
    for (int kt = 0; kt < nk; kt++) {
        const int cur = kt & 1;
        const int nxt = cur ^ 1;
        if (kt + 1 < nk) {
            a4 = *(const float4*)(Aptr + (kt + 1) * BK);
            b4 = *(const float4*)(Wptr + (kt + 1) * BK);
        }
        #pragma unroll
        for (int kk = 0; kk < BK; kk++) {
            float af[8], bf[8];
            *(float4*)&af[0] = *(const float4*)&As[cur][kk][ty*4];
            *(float4*)&af[4] = *(const float4*)&As[cur][kk][64 + ty*4];
            *(float4*)&bf[0] = *(const float4*)&Bs[cur][kk][tx*4];
            *(float4*)&bf[4] = *(const float4*)&Bs[cur][kk][64 + tx*4];
            #pragma unroll
            for (int i = 0; i < 8; i++)
                #pragma unroll
                for (int j = 0; j < 8; j++)
                    acc[i][j] += af[i] * bf[j];
        }
        if (kt + 1 < nk) {
            As[nxt][lk+0][lr] = a4.x; As[nxt][lk+1][lr] = a4.y;
            As[nxt][lk+2][lr] = a4.z; As[nxt][lk+3][lr] = a4.w;
            Bs[nxt][lk+0][lr] = b4.x; Bs[nxt][lk+1][lr] = b4.y;
            Bs[nxt][lk+2][lr] = b4.z; Bs[nxt][lk+3][lr] = b4.w;
            __syncthreads();
        }
    }

    // epilogue
    #pragma unroll
    for (int i = 0; i < 8; i++) {
        const int row = bm + ((i < 4) ? (ty*4 + i) : (64 + ty*4 + i - 4));
        #pragma unroll
        for (int jg = 0; jg < 2; jg++) {
            const int col = bn + jg*64 + tx*4;
            float4 bsv = *(const float4*)(bias + col);
            float4 v;
            v.x = acc[i][jg*4+0] + bsv.x;
            v.y = acc[i][jg*4+1] + bsv.y;
            v.z = acc[i][jg*4+2] + bsv.z;
            v.w = acc[i][jg*4+3] + bsv.w;
            if (res) {
                float4 rv = *(const float4*)(res + row * N + col);
                v.x += rv.x; v.y += rv.y; v.z += rv.z; v.w += rv.w;
            }
            *(float4*)(C + row * N + col) = v;
        }
    }
}

// ---------------------------------------------------------------------------
// Banded attention: one warp per (b, h, s); band |s-t|<=3 (exact: masked
// entries underflow to exactly 0 in the reference softmax)
// ---------------------------------------------------------------------------
__global__ void attn_kernel(const float* __restrict__ Q,
                            const float* __restrict__ K,
                            const float* __restrict__ V,
                            float* __restrict__ O) {
    const int gw = (blockIdx.x * blockDim.x + threadIdx.x) >> 5;
    const int lane = threadIdx.x & 31;
    const int h = gw & 7;
    const int s = (gw >> 3) & 255;
    const int b = gw >> 11;

    const int base = (b * TT) * DD + h * DKk + lane * 4;
    const float4 q4 = *(const float4*)(Q + base + s * DD);

    const int t0 = max(s - 3, 0);
    const int t1 = min(s + 3, TT - 1);

    float sc[7];
    float m = -1e30f;
    for (int t = t0; t <= t1; t++) {
        const float4 k4 = *(const float4*)(K + base + t * DD);
        float p = q4.x*k4.x + q4.y*k4.y + q4.z*k4.z + q4.w*k4.w;
        p += __shfl_xor_sync(0xffffffffu, p, 16);
        p += __shfl_xor_sync(0xffffffffu, p, 8);
        p += __shfl_xor_sync(0xffffffffu, p, 4);
        p += __shfl_xor_sync(0xffffffffu, p, 2);
        p += __shfl_xor_sync(0xffffffffu, p, 1);
        p *= 0.088388347648318447f;  // 1/sqrt(128)
        sc[t - t0] = p;
        m = fmaxf(m, p);
    }
    float sum = 0.0f;
    for (int t = t0; t <= t1; t++) {
        const float e = __expf(sc[t - t0] - m);
        sc[t - t0] = e;
        sum += e;
    }
    const float inv = 1.0f / sum;
    float4 o = make_float4(0.f, 0.f, 0.f, 0.f);
    for (int t = t0; t <= t1; t++) {
        const float w = sc[t - t0] * inv;
        const float4 v4 = *(const float4*)(V + base + t * DD);
        o.x += w * v4.x; o.y += w * v4.y; o.z += w * v4.z; o.w += w * v4.w;
    }
    *(float4*)(O + base + s * DD) = o;
}

// ---------------------------------------------------------------------------
// BiGRU persistent kernel: 128 blocks (64 fwd, 64 bwd), 256 threads each.
// Block owns 4 hidden units; W_hh rows (12x256) resident in smem; h state
// ping-pongs through L2 (ldcg/stcg) with a software grid barrier per step.
// ---------------------------------------------------------------------------
__device__ __forceinline__ float sigmoidf_(float x) {
    return 1.0f / (1.0f + expf(-x));
}

__global__ __launch_bounds__(256, 1)
void gru_kernel(const float* __restrict__ GF, const float* __restrict__ GB,
                const float* __restrict__ Whhf, const float* __restrict__ Whhb,
                const float* __restrict__ bhhf, const float* __restrict__ bhhb,
                const int* __restrict__ seglen, float* __restrict__ out) {
    const int dir = blockIdx.x >> 6;           // 0 fwd, 1 bwd
    const int jbase = (blockIdx.x & 63) * 4;
    const float* W  = dir ? Whhb : Whhf;
    const float* bh = dir ? bhhb : bhhf;
    const float* GX = dir ? GB : GF;

    __shared__ float4 sW[12][65];   // 12 gate rows x 64 float4 (K=256), padded
    __shared__ float4 sh[64][33];   // h phase tile: [b][k4] (128 k per phase)
    __shared__ float  sb[12];
    __shared__ int    slen[64];

    const int tid = threadIdx.x;
    const int b  = tid >> 2;
    const int jj = tid & 3;

    // load W_hh rows + biases + lens
    for (int idx = tid; idx < 12 * 64; idx += 256) {
        const int gl = idx >> 6;        // 0..11 : gate*4 + jj
        const int k4 = idx & 63;
        const int gate = gl >> 2;
        const int ju = gl & 3;
        const int grow = gate * GH + jbase + ju;
        sW[gl][k4] = *(const float4*)(W + grow * GH + k4 * 4);
    }
    if (tid < 12) {
        const int gate = tid >> 2, ju = tid & 3;
        sb[tid] = bh[gate * GH + jbase + ju];
    }
    if (tid < 64) slen[tid] = seglen[tid];
    __syncthreads();

    unsigned target = 0;
    for (int t = 0; t < TT; t++) {
        const int p = t & 1;
        const float* hp = g_H + ((dir * 2 + p) * BB) * GH;
        float* hn = g_H + ((dir * 2 + (p ^ 1)) * BB) * GH;

        float accr = sb[jj], accz = sb[4 + jj], accn = sb[8 + jj];

        #pragma unroll
        for (int phase = 0; phase < 2; phase++) {
            __syncthreads();
            // fill sh: 64 b x 32 float4
            for (int i = 0; i < 8; i++) {
                const int idx = tid + i * 256;
                const int lb = idx >> 5;
                const int lk = idx & 31;
                sh[lb][lk] = __ldcg((const float4*)(hp + lb * GH + phase * 128) + lk);
            }
            __syncthreads();
            #pragma unroll
            for (int k4 = 0; k4 < 32; k4++) {
                const float4 hv = sh[b][k4];
                const float4 wr = sW[jj][phase * 32 + k4];
                const float4 wz = sW[4 + jj][phase * 32 + k4];
                const float4 wn = sW[8 + jj][phase * 32 + k4];
                accr += hv.x*wr.x + hv.y*wr.y + hv.z*wr.z + hv.w*wr.w;
                accz += hv.x*wz.x + hv.y*wz.y + hv.z*wz.z + hv.w*wz.w;
                accn += hv.x*wn.x + hv.y*wn.y + hv.z*wn.z + hv.w*wn.w;
            }
        }

        const int len = slen[b];
        const bool valid = (t < len);
        const int te = dir ? (len - 1 - t) : t;
        const int row = b * TT + (valid ? te : 0);
        const int jglob = jbase + jj;

        const float xr = GX[row * G3 + jglob];
        const float xz = GX[row * G3 + GH + jglob];
        const float xn = GX[row * G3 + 2 * GH + jglob];
        const float hpj = __ldcg(hp + b * GH + jglob);

        const float r = sigmoidf_(xr + accr);
        const float z = sigmoidf_(xz + accz);
        const float n = tanhf(xn + r * accn);
        const float hnew = valid ? ((1.0f - z) * n + z * hpj) : hpj;

        __stcg(hn + b * GH + jglob, hnew);
        if (valid)
            out[(b * TT + te) * 512 + dir * GH + jglob] = hnew;

        // grid barrier (monotonic counter; 128 co-resident blocks)
        target += 128;
        __syncthreads();
        __threadfence();
        if (tid == 0) {
            atomicAdd(&g_bar, 1u);
            while (*(volatile unsigned*)&g_bar < target) { }
            __threadfence();
        }
        __syncthreads();
    }
}

// ---------------------------------------------------------------------------
extern "C" void kernel_launch(void* const* d_in, const int* in_sizes, int n_in,
                              void* d_out, int out_size) {
    const float* seg   = (const float*)d_in[0];
    const int*   slen  = (const int*)  d_in[1];
    const float* Wq    = (const float*)d_in[2];
    const float* bq    = (const float*)d_in[3];
    const float* Wk    = (const float*)d_in[4];
    const float* bk    = (const float*)d_in[5];
    const float* Wv    = (const float*)d_in[6];
    const float* bv    = (const float*)d_in[7];
    const float* Wo    = (const float*)d_in[8];
    const float* bo    = (const float*)d_in[9];
    const float* Wihf  = (const float*)d_in[10];
    const float* Whhf  = (const float*)d_in[11];
    const float* bihf  = (const float*)d_in[12];
    const float* bhhf  = (const float*)d_in[13];
    const float* Wihb  = (const float*)d_in[14];
    const float* Whhb  = (const float*)d_in[15];
    const float* bihb  = (const float*)d_in[16];
    const float* bhhb  = (const float*)d_in[17];
    float* out = (float*)d_out;

    float *pX, *pQ, *pK, *pV, *pAO, *pGF, *pGB;
    cudaGetSymbolAddress((void**)&pX,  g_X);
    cudaGetSymbolAddress((void**)&pQ,  g_Q);
    cudaGetSymbolAddress((void**)&pK,  g_K);
    cudaGetSymbolAddress((void**)&pV,  g_V);
    cudaGetSymbolAddress((void**)&pAO, g_AO);
    cudaGetSymbolAddress((void**)&pGF, g_GF);
    cudaGetSymbolAddress((void**)&pGB, g_GB);

    init_kernel<<<512, 256>>>(out, out_size);

    const dim3 gD(DD / BN, MROWS / BM);    // N=1024
    const dim3 gG(G3 / BN, MROWS / BM);    // N=768
    const dim3 blk(256);
    const int attnBlocks = (BB * TT * HH) / 8;   // 8 warps/block

    // ---- layer 0 ----
    sgemm_bias<<<gD, blk>>>(seg, Wq, bq, nullptr, pQ, DD, DD);
    sgemm_bias<<<gD, blk>>>(seg, Wk, bk, nullptr, pK, DD, DD);
    sgemm_bias<<<gD, blk>>>(seg, Wv, bv, nullptr, pV, DD, DD);
    attn_kernel<<<attnBlocks, blk>>>(pQ, pK, pV, pAO);
    sgemm_bias<<<gD, blk>>>(pAO, Wo, bo, seg, pX, DD, DD);

    // ---- layer 1 ----
    const float* Wq1 = Wq + DD * DD; const float* bq1 = bq + DD;
    const float* Wk1 = Wk + DD * DD; const float* bk1 = bk + DD;
    const float* Wv1 = Wv + DD * DD; const float* bv1 = bv + DD;
    const float* Wo1 = Wo + DD * DD; const float* bo1 = bo + DD;
    sgemm_bias<<<gD, blk>>>(pX, Wq1, bq1, nullptr, pQ, DD, DD);
    sgemm_bias<<<gD, blk>>>(pX, Wk1, bk1, nullptr, pK, DD, DD);
    sgemm_bias<<<gD, blk>>>(pX, Wv1, bv1, nullptr, pV, DD, DD);
    attn_kernel<<<attnBlocks, blk>>>(pQ, pK, pV, pAO);
    sgemm_bias<<<gD, blk>>>(pAO, Wo1, bo1, pX, pX, DD, DD);

    // ---- GRU input projections ----
    sgemm_bias<<<gG, blk>>>(pX, Wihf, bihf, nullptr, pGF, G3, DD);
    sgemm_bias<<<gG, blk>>>(pX, Wihb, bihb, nullptr, pGB, G3, DD);

    // ---- BiGRU recurrence (persistent, grid-barriered) ----
    gru_kernel<<<128, 256>>>(pGF, pGB, Whhf, Whhb, bhhf, bhhb, slen, out);
}

// round 5
// speedup vs baseline: 1.5917x; 1.5917x over previous
#include <cuda_runtime.h>
#include <cuda_bf16.h>
#include <math.h>
#include <stdint.h>

#define BB 64
#define TT 256
#define DD 1024
#define HH 8
#define GH 256
#define G3 768
#define MROWS (BB*TT)   // 16384

// ---------------- scratch (device globals; allocation forbidden) -----------
__device__ float g_Ar [MROWS*DD];        // rounded A mirror (seg_r / X_r)
__device__ float g_AOr[MROWS*DD];        // rounded attention output
__device__ float g_Xf [MROWS*DD];        // fp32 X after layer0 (residual for layer1)
__device__ float g_QKV[MROWS*3072];      // fused QKV output (fp32)
__device__ float g_G  [MROWS*1536];      // fused GRU gx (fwd|bwd), fp32
__device__ float g_W  [9961472];         // rounded concat weights
__device__ float g_bias[9728];           // concat biases
__device__ float g_H [2*2*BB*GH];        // [dir][parity][b][GH]
__device__ unsigned g_bar;

// Weight region offsets (floats)
#define W_QKV0 0
#define W_O0   3145728
#define W_QKV1 4194304
#define W_O1   7340032
#define W_GRU  8388608
// Bias offsets
#define B_QKV0 0
#define B_O0   3072
#define B_QKV1 4096
#define B_O1   7168
#define B_GRU  8192

// ---------------------------------------------------------------------------
__device__ __forceinline__ float tf32r(float x) {
    uint32_t u;
    asm("cvt.rna.tf32.f32 %0, %1;" : "=r"(u) : "f"(x));
    return __uint_as_float(u);
}

__device__ __forceinline__ uint32_t smem_u32(const void* p) {
    uint32_t a;
    asm("{ .reg .u64 t; cvta.to.shared.u64 t, %1; cvt.u32.u64 %0, t; }" : "=r"(a) : "l"(p));
    return a;
}
__device__ __forceinline__ void cp_async16(uint32_t dst_smem, const void* src) {
    asm volatile("cp.async.cg.shared.global [%0], [%1], 16;" :: "r"(dst_smem), "l"(src));
}
#define CP_COMMIT() asm volatile("cp.async.commit_group;" ::: "memory")
#define CP_WAIT1()  asm volatile("cp.async.wait_group 1;" ::: "memory")
#define CP_WAIT0()  asm volatile("cp.async.wait_group 0;" ::: "memory")

__device__ __forceinline__ void mma_tf32(float* d, const uint32_t* a, const uint32_t* b) {
    asm volatile(
        "mma.sync.aligned.m16n8k8.row.col.f32.tf32.tf32.f32 "
        "{%0,%1,%2,%3}, {%4,%5,%6,%7}, {%8,%9}, {%0,%1,%2,%3};"
        : "+f"(d[0]), "+f"(d[1]), "+f"(d[2]), "+f"(d[3])
        : "r"(a[0]), "r"(a[1]), "r"(a[2]), "r"(a[3]), "r"(b[0]), "r"(b[1]));
}

// ---------------------------------------------------------------------------
// init + prep
// ---------------------------------------------------------------------------
__global__ void init_kernel(float* out, int out_n) {
    int i = blockIdx.x * blockDim.x + threadIdx.x;
    int stride = gridDim.x * blockDim.x;
    for (int k = i; k < out_n; k += stride) out[k] = 0.0f;
    for (int k = i; k < BB*GH; k += stride) {
        g_H[(0*2+0)*BB*GH + k] = 0.0f;
        g_H[(1*2+0)*BB*GH + k] = 0.0f;
    }
    if (i == 0) g_bar = 0u;
}

__global__ void round_copy(const float* __restrict__ src, float* __restrict__ dst, int n4) {
    int i = blockIdx.x * blockDim.x + threadIdx.x;
    int stride = gridDim.x * blockDim.x;
    for (int k = i; k < n4; k += stride) {
        float4 v = ((const float4*)src)[k];
        v.x = tf32r(v.x); v.y = tf32r(v.y); v.z = tf32r(v.z); v.w = tf32r(v.w);
        ((float4*)dst)[k] = v;
    }
}

// ---------------------------------------------------------------------------
// tf32 mma.sync GEMM: C[M,Nc] = A[M,1024] @ W[Nc,1024]^T + bias (+res)
// BM=128, BN=128, BK=32, 8 warps (2x4), warp tile 64x32, 3-stage cp.async
// ---------------------------------------------------------------------------
#define SK 36                      // padded smem row stride (floats)
#define STG_FLOATS (128*SK)        // per-operand per-stage floats (4608)
#define GEMM_SMEM (3 * 2 * STG_FLOATS * 4)   // 110592 bytes

__global__ __launch_bounds__(256, 1)
void mma_gemm(const float* __restrict__ A, const float* __restrict__ Wp,
              const float* __restrict__ bias, const float* __restrict__ res,
              float* __restrict__ Cf, float* __restrict__ Cr, int Nc) {
    extern __shared__ float sm[];
    const uint32_t sbase = smem_u32(sm);
    const int tid  = threadIdx.x;
    const int wid  = tid >> 5;
    const int lane = tid & 31;
    const int warp_m = wid & 1;        // 0..1
    const int warp_n = wid >> 1;       // 0..3
    const int gid = lane >> 2;
    const int tig = lane & 3;
    const int bm = blockIdx.y * 128;
    const int bn = blockIdx.x * 128;

    // per-thread cp.async assignments
    const int ldr = tid >> 1;                 // 0..127 : row
    const int ldc = (tid & 1) << 1;           // 0 or 2 : chunk pair base

    auto load_stage = [&](int kt, int p) {
        const uint32_t sA = sbase + p * 2 * STG_FLOATS * 4;
        const uint32_t sB = sA + STG_FLOATS * 4;
        const float* ga = A  + (long)(bm + ldr) * DD + kt * 32;
        const float* gb = Wp + (long)(bn + ldr) * DD + kt * 32;
        #pragma unroll
        for (int c = 0; c < 4; c++) {
            // chunks ldc, ldc+1, ldc+4, ldc+5 (two threads cover 8 chunks/row)
            const int ch = ((c & 1) ? (ldc + 1) : ldc) + ((c >> 1) << 2);
            cp_async16(sA + (ldr * SK + ch * 4) * 4, ga + ch * 4);
            cp_async16(sB + (ldr * SK + ch * 4) * 4, gb + ch * 4);
        }
    };

    float acc[4][4][4];
    #pragma unroll
    for (int mt = 0; mt < 4; mt++)
        #pragma unroll
        for (int nt = 0; nt < 4; nt++)
            #pragma unroll
            for (int q = 0; q < 4; q++) acc[mt][nt][q] = 0.0f;

    const int NK = DD / 32;   // 32
    load_stage(0, 0); CP_COMMIT();
    load_stage(1, 1); CP_COMMIT();

    for (int kt = 0; kt < NK; kt++) {
        CP_WAIT1();
        __syncthreads();
        if (kt + 2 < NK) load_stage(kt + 2, (kt + 2) % 3);
        CP_COMMIT();

        const float* sA = sm + (kt % 3) * 2 * STG_FLOATS;
        const float* sB = sA + STG_FLOATS;
        const int mb = warp_m * 64;
        const int nb = warp_n * 32;
        #pragma unroll
        for (int ks = 0; ks < 4; ks++) {
            const int k0 = ks * 8;
            uint32_t afr[4][4], bfr[4][2];
            #pragma unroll
            for (int mt = 0; mt < 4; mt++) {
                const int r = mb + mt * 16;
                afr[mt][0] = __float_as_uint(sA[(r + gid    ) * SK + k0 + tig    ]);
                afr[mt][1] = __float_as_uint(sA[(r + gid + 8) * SK + k0 + tig    ]);
                afr[mt][2] = __float_as_uint(sA[(r + gid    ) * SK + k0 + tig + 4]);
                afr[mt][3] = __float_as_uint(sA[(r + gid + 8) * SK + k0 + tig + 4]);
            }
            #pragma unroll
            for (int nt = 0; nt < 4; nt++) {
                const int c = nb + nt * 8;
                bfr[nt][0] = __float_as_uint(sB[(c + gid) * SK + k0 + tig    ]);
                bfr[nt][1] = __float_as_uint(sB[(c + gid) * SK + k0 + tig + 4]);
            }
            #pragma unroll
            for (int mt = 0; mt < 4; mt++)
                #pragma unroll
                for (int nt = 0; nt < 4; nt++)
                    mma_tf32(acc[mt][nt], afr[mt], bfr[nt]);
        }
        __syncthreads();
    }
    CP_WAIT0();

    // epilogue: c0,c1 -> (row, col..col+1); c2,c3 -> (row+8, col..col+1)
    #pragma unroll
    for (int mt = 0; mt < 4; mt++) {
        #pragma unroll
        for (int nt = 0; nt < 4; nt++) {
            const long row0 = bm + warp_m * 64 + mt * 16 + gid;
            const int  colg = bn + warp_n * 32 + nt * 8 + 2 * tig;
            #pragma unroll
            for (int half = 0; half < 2; half++) {
                const long row = row0 + half * 8;
                float2 v;
                v.x = acc[mt][nt][half * 2 + 0];
                v.y = acc[mt][nt][half * 2 + 1];
                const float2 bv = *(const float2*)(bias + colg);
                v.x += bv.x; v.y += bv.y;
                if (res) {
                    const float2 rv = *(const float2*)(res + row * Nc + colg);
                    v.x += rv.x; v.y += rv.y;
                }
                if (Cf) *(float2*)(Cf + row * Nc + colg) = v;
                if (Cr) {
                    float2 w;
                    w.x = tf32r(v.x); w.y = tf32r(v.y);
                    *(float2*)(Cr + row * Nc + colg) = w;
                }
            }
        }
    }
}

// ---------------------------------------------------------------------------
// Banded attention over fused QKV (stride 3072); writes rounded output
// ---------------------------------------------------------------------------
__global__ void attn_kernel(const float* __restrict__ QKV, float* __restrict__ Or) {
    const int gw = (blockIdx.x * blockDim.x + threadIdx.x) >> 5;
    const int lane = threadIdx.x & 31;
    const int h = gw & 7;
    const int s = (gw >> 3) & 255;
    const int b = gw >> 11;

    const long rb = (long)(b * TT) * 3072 + h * 128 + lane * 4;
    const float4 q4 = *(const float4*)(QKV + rb + (long)s * 3072);

    const int t0 = max(s - 3, 0);
    const int t1 = min(s + 3, TT - 1);

    float sc[7];
    float m = -1e30f;
    for (int t = t0; t <= t1; t++) {
        const float4 k4 = *(const float4*)(QKV + rb + 1024 + (long)t * 3072);
        float p = q4.x*k4.x + q4.y*k4.y + q4.z*k4.z + q4.w*k4.w;
        p += __shfl_xor_sync(0xffffffffu, p, 16);
        p += __shfl_xor_sync(0xffffffffu, p, 8);
        p += __shfl_xor_sync(0xffffffffu, p, 4);
        p += __shfl_xor_sync(0xffffffffu, p, 2);
        p += __shfl_xor_sync(0xffffffffu, p, 1);
        p *= 0.088388347648318447f;
        sc[t - t0] = p;
        m = fmaxf(m, p);
    }
    float sum = 0.0f;
    for (int t = t0; t <= t1; t++) {
        const float e = __expf(sc[t - t0] - m);
        sc[t - t0] = e;
        sum += e;
    }
    const float inv = 1.0f / sum;
    float4 o = make_float4(0.f, 0.f, 0.f, 0.f);
    for (int t = t0; t <= t1; t++) {
        const float w = sc[t - t0] * inv;
        const float4 v4 = *(const float4*)(QKV + rb + 2048 + (long)t * 3072);
        o.x += w * v4.x; o.y += w * v4.y; o.z += w * v4.z; o.w += w * v4.w;
    }
    o.x = tf32r(o.x); o.y = tf32r(o.y); o.z = tf32r(o.z); o.w = tf32r(o.w);
    *(float4*)(Or + (long)(b * TT + s) * 1024 + h * 128 + lane * 4) = o;
}

// ---------------------------------------------------------------------------
// BiGRU persistent kernel (reads fused gx with stride 1536)
// ---------------------------------------------------------------------------
__device__ __forceinline__ float sigmoidf_(float x) { return 1.0f / (1.0f + expf(-x)); }

__global__ __launch_bounds__(256, 1)
void gru_kernel(const float* __restrict__ G,
                const float* __restrict__ Whhf, const float* __restrict__ Whhb,
                const float* __restrict__ bhhf, const float* __restrict__ bhhb,
                const int* __restrict__ seglen, float* __restrict__ out) {
    const int dir = blockIdx.x >> 6;
    const int jbase = (blockIdx.x & 63) * 4;
    const float* W  = dir ? Whhb : Whhf;
    const float* bh = dir ? bhhb : bhhf;

    __shared__ float4 sW[12][65];
    __shared__ float4 sh[64][33];
    __shared__ float  sb[12];
    __shared__ int    slen[64];

    const int tid = threadIdx.x;
    const int b  = tid >> 2;
    const int jj = tid & 3;

    for (int idx = tid; idx < 12 * 64; idx += 256) {
        const int gl = idx >> 6;
        const int k4 = idx & 63;
        const int gate = gl >> 2;
        const int ju = gl & 3;
        sW[gl][k4] = *(const float4*)(W + (gate * GH + jbase + ju) * GH + k4 * 4);
    }
    if (tid < 12) sb[tid] = bh[(tid >> 2) * GH + jbase + (tid & 3)];
    if (tid < 64) slen[tid] = seglen[tid];
    __syncthreads();

    unsigned target = 0;
    for (int t = 0; t < TT; t++) {
        const int p = t & 1;
        const float* hp = g_H + ((dir * 2 + p) * BB) * GH;
        float* hn = g_H + ((dir * 2 + (p ^ 1)) * BB) * GH;

        float accr = sb[jj], accz = sb[4 + jj], accn = sb[8 + jj];

        #pragma unroll
        for (int phase = 0; phase < 2; phase++) {
            __syncthreads();
            for (int i = 0; i < 8; i++) {
                const int idx = tid + i * 256;
                const int lb = idx >> 5;
                const int lk = idx & 31;
                sh[lb][lk] = __ldcg((const float4*)(hp + lb * GH + phase * 128) + lk);
            }
            __syncthreads();
            #pragma unroll
            for (int k4 = 0; k4 < 32; k4++) {
                const float4 hv = sh[b][k4];
                const float4 wr = sW[jj][phase * 32 + k4];
                const float4 wz = sW[4 + jj][phase * 32 + k4];
                const float4 wn = sW[8 + jj][phase * 32 + k4];
                accr += hv.x*wr.x + hv.y*wr.y + hv.z*wr.z + hv.w*wr.w;
                accz += hv.x*wz.x + hv.y*wz.y + hv.z*wz.z + hv.w*wz.w;
                accn += hv.x*wn.x + hv.y*wn.y + hv.z*wn.z + hv.w*wn.w;
            }
        }

        const int len = slen[b];
        const bool valid = (t < len);
        const int te = dir ? (len - 1 - t) : t;
        const int row = b * TT + (valid ? te : 0);
        const int jglob = jbase + jj;

        const float xr = G[(long)row * 1536 + dir * G3 + jglob];
        const float xz = G[(long)row * 1536 + dir * G3 + GH + jglob];
        const float xn = G[(long)row * 1536 + dir * G3 + 2 * GH + jglob];
        const float hpj = __ldcg(hp + b * GH + jglob);

        const float r = sigmoidf_(xr + accr);
        const float z = sigmoidf_(xz + accz);
        const float n = tanhf(xn + r * accn);
        const float hnew = valid ? ((1.0f - z) * n + z * hpj) : hpj;

        __stcg(hn + b * GH + jglob, hnew);
        if (valid)
            out[(long)(b * TT + te) * 512 + dir * GH + jglob] = hnew;

        target += 128;
        __syncthreads();
        __threadfence();
        if (tid == 0) {
            atomicAdd(&g_bar, 1u);
            while (*(volatile unsigned*)&g_bar < target) __nanosleep(64);
            __threadfence();
        }
        __syncthreads();
    }
}

// ---------------------------------------------------------------------------
extern "C" void kernel_launch(void* const* d_in, const int* in_sizes, int n_in,
                              void* d_out, int out_size) {
    const float* seg   = (const float*)d_in[0];
    const int*   slen  = (const int*)  d_in[1];
    const float* Wq    = (const float*)d_in[2];
    const float* bq    = (const float*)d_in[3];
    const float* Wk    = (const float*)d_in[4];
    const float* bk    = (const float*)d_in[5];
    const float* Wv    = (const float*)d_in[6];
    const float* bv    = (const float*)d_in[7];
    const float* Wo    = (const float*)d_in[8];
    const float* bo    = (const float*)d_in[9];
    const float* Wihf  = (const float*)d_in[10];
    const float* Whhf  = (const float*)d_in[11];
    const float* bihf  = (const float*)d_in[12];
    const float* bhhf  = (const float*)d_in[13];
    const float* Wihb  = (const float*)d_in[14];
    const float* Whhb  = (const float*)d_in[15];
    const float* bihb  = (const float*)d_in[16];
    const float* bhhb  = (const float*)d_in[17];
    float* out = (float*)d_out;

    float *pAr, *pAOr, *pXf, *pQKV, *pG, *pW, *pBias;
    cudaGetSymbolAddress((void**)&pAr,   g_Ar);
    cudaGetSymbolAddress((void**)&pAOr,  g_AOr);
    cudaGetSymbolAddress((void**)&pXf,   g_Xf);
    cudaGetSymbolAddress((void**)&pQKV,  g_QKV);
    cudaGetSymbolAddress((void**)&pG,    g_G);
    cudaGetSymbolAddress((void**)&pW,    g_W);
    cudaGetSymbolAddress((void**)&pBias, g_bias);

    cudaFuncSetAttribute(mma_gemm, cudaFuncAttributeMaxDynamicSharedMemorySize, GEMM_SMEM);

    init_kernel<<<512, 256>>>(out, out_size);

    // ---- prep: rounded A mirror + rounded concatenated weights ----
    const int MW = 1024 * 1024;
    round_copy<<<512, 256>>>(seg, pAr, (MROWS * DD) / 4);
    round_copy<<<256, 256>>>(Wq,            pW + W_QKV0,            MW / 4);
    round_copy<<<256, 256>>>(Wk,            pW + W_QKV0 + MW,       MW / 4);
    round_copy<<<256, 256>>>(Wv,            pW + W_QKV0 + 2*MW,     MW / 4);
    round_copy<<<256, 256>>>(Wo,            pW + W_O0,              MW / 4);
    round_copy<<<256, 256>>>(Wq + MW,       pW + W_QKV1,            MW / 4);
    round_copy<<<256, 256>>>(Wk + MW,       pW + W_QKV1 + MW,       MW / 4);
    round_copy<<<256, 256>>>(Wv + MW,       pW + W_QKV1 + 2*MW,     MW / 4);
    round_copy<<<256, 256>>>(Wo + MW,       pW + W_O1,              MW / 4);
    round_copy<<<256, 256>>>(Wihf,          pW + W_GRU,             (G3 * DD) / 4);
    round_copy<<<256, 256>>>(Wihb,          pW + W_GRU + G3 * DD,   (G3 * DD) / 4);

    // ---- concat biases ----
    cudaMemcpyAsync(pBias + B_QKV0,          bq,        DD*4, cudaMemcpyDeviceToDevice);
    cudaMemcpyAsync(pBias + B_QKV0 + 1024,   bk,        DD*4, cudaMemcpyDeviceToDevice);
    cudaMemcpyAsync(pBias + B_QKV0 + 2048,   bv,        DD*4, cudaMemcpyDeviceToDevice);
    cudaMemcpyAsync(pBias + B_O0,            bo,        DD*4, cudaMemcpyDeviceToDevice);
    cudaMemcpyAsync(pBias + B_QKV1,          bq + DD,   DD*4, cudaMemcpyDeviceToDevice);
    cudaMemcpyAsync(pBias + B_QKV1 + 1024,   bk + DD,   DD*4, cudaMemcpyDeviceToDevice);
    cudaMemcpyAsync(pBias + B_QKV1 + 2048,   bv + DD,   DD*4, cudaMemcpyDeviceToDevice);
    cudaMemcpyAsync(pBias + B_O1,            bo + DD,   DD*4, cudaMemcpyDeviceToDevice);
    cudaMemcpyAsync(pBias + B_GRU,           bihf,      G3*4, cudaMemcpyDeviceToDevice);
    cudaMemcpyAsync(pBias + B_GRU + G3,      bihb,      G3*4, cudaMemcpyDeviceToDevice);

    const dim3 blk(256);
    const dim3 gQKV(3072 / 128, MROWS / 128);
    const dim3 gO  (1024 / 128, MROWS / 128);
    const dim3 gG_ (1536 / 128, MROWS / 128);
    const int attnBlocks = (BB * TT * HH) / 8;

    // layer 0
    mma_gemm<<<gQKV, blk, GEMM_SMEM>>>(pAr,  pW + W_QKV0, pBias + B_QKV0, nullptr, pQKV, nullptr, 3072);
    attn_kernel<<<attnBlocks, blk>>>(pQKV, pAOr);
    mma_gemm<<<gO,   blk, GEMM_SMEM>>>(pAOr, pW + W_O0,   pBias + B_O0,   seg,     pXf,  pAr,    1024);
    // layer 1
    mma_gemm<<<gQKV, blk, GEMM_SMEM>>>(pAr,  pW + W_QKV1, pBias + B_QKV1, nullptr, pQKV, nullptr, 3072);
    attn_kernel<<<attnBlocks, blk>>>(pQKV, pAOr);
    mma_gemm<<<gO,   blk, GEMM_SMEM>>>(pAOr, pW + W_O1,   pBias + B_O1,   pXf,     nullptr, pAr,  1024);
    // GRU input projections (fused fwd|bwd)
    mma_gemm<<<gG_,  blk, GEMM_SMEM>>>(pAr,  pW + W_GRU,  pBias + B_GRU,  nullptr, pG,   nullptr, 1536);

    // BiGRU recurrence
    gru_kernel<<<128, 256>>>(pG, Whhf, Whhb, bhhf, bhhb, slen, out);
}

// round 7
// speedup vs baseline: 2.3532x; 1.4784x over previous
#include <cuda_runtime.h>
#include <cuda_fp16.h>
#include <math.h>
#include <stdint.h>

#define BB 64
#define TT 256
#define DD 1024
#define HH 8
#define GH 256
#define G3 768
#define MROWS (BB*TT)   // 16384

// ---------------- scratch (device globals; allocation forbidden) -----------
__device__ __align__(16) __half g_Ah [MROWS*DD];   // fp16 A mirror (seg_h / X_h)
__device__ __align__(16) __half g_AOh[MROWS*DD];   // fp16 attention output
__device__ __align__(16) float  g_Xf [MROWS*DD];   // fp32 X after layer0
__device__ __align__(16) float  g_QKV[MROWS*3072]; // fused QKV output (fp32)
__device__ __align__(16) float  g_G  [MROWS*1536]; // fused GRU gx (fwd|bwd), fp32
__device__ __align__(16) __half g_Wh [9961472];    // fp16 concat weights
__device__ __align__(16) float  g_bias[9728];      // concat biases (fp32)
__device__ __align__(16) float  g_H [2*2*BB*GH];   // [dir][parity][b][GH]
__device__ unsigned g_bar;

// Weight region offsets (elements)
#define W_QKV0 0
#define W_O0   3145728
#define W_QKV1 4194304
#define W_O1   7340032
#define W_GRU  8388608
// Bias offsets
#define B_QKV0 0
#define B_O0   3072
#define B_QKV1 4096
#define B_O1   7168
#define B_GRU  8192

// ---------------------------------------------------------------------------
__device__ __forceinline__ uint32_t smem_u32(const void* p) {
    uint32_t a;
    asm("{ .reg .u64 t; cvta.to.shared.u64 t, %1; cvt.u32.u64 %0, t; }" : "=r"(a) : "l"(p));
    return a;
}
__device__ __forceinline__ void cp_async16(uint32_t dst_smem, const void* src) {
    asm volatile("cp.async.cg.shared.global [%0], [%1], 16;" :: "r"(dst_smem), "l"(src));
}
#define CP_COMMIT() asm volatile("cp.async.commit_group;" ::: "memory")
#define CP_WAIT1()  asm volatile("cp.async.wait_group 1;" ::: "memory")

__device__ __forceinline__ void mma_f16(float* d, const uint32_t* a, const uint32_t* b) {
    asm volatile(
        "mma.sync.aligned.m16n8k16.row.col.f32.f16.f16.f32 "
        "{%0,%1,%2,%3}, {%4,%5,%6,%7}, {%8,%9}, {%0,%1,%2,%3};"
        : "+f"(d[0]), "+f"(d[1]), "+f"(d[2]), "+f"(d[3])
        : "r"(a[0]), "r"(a[1]), "r"(a[2]), "r"(a[3]), "r"(b[0]), "r"(b[1]));
}

// ---------------------------------------------------------------------------
// init (h state + barrier only; out padding handled by gru kernel)
// ---------------------------------------------------------------------------
__global__ void init_kernel() {
    int i = blockIdx.x * blockDim.x + threadIdx.x;
    int stride = gridDim.x * blockDim.x;
    for (int k = i; k < BB*GH; k += stride) {
        g_H[(0*2+0)*BB*GH + k] = 0.0f;
        g_H[(1*2+0)*BB*GH + k] = 0.0f;
    }
    if (i == 0) g_bar = 0u;
}

__global__ void to_half(const float* __restrict__ src, __half* __restrict__ dst, int n4) {
    int i = blockIdx.x * blockDim.x + threadIdx.x;
    int stride = gridDim.x * blockDim.x;
    for (int k = i; k < n4; k += stride) {
        float4 v = ((const float4*)src)[k];
        __half2 h01 = __floats2half2_rn(v.x, v.y);
        __half2 h23 = __floats2half2_rn(v.z, v.w);
        uint2 u;
        u.x = *(uint32_t*)&h01;
        u.y = *(uint32_t*)&h23;
        ((uint2*)dst)[k] = u;
    }
}

// ---------------------------------------------------------------------------
// fp16 mma.sync GEMM: C[M,Nc] = A[M,1024] @ W[Nc,1024]^T + bias (+res)
// BM=128, BN=128, BK=32, 8 warps (2x4), warp tile 64x32, 3-stage cp.async
// smem rows: 32 halves = 16 b32 + 4 pad -> stride 20 b32 (80B: 16B-aligned,
// and 20*gid+tig covers all 32 banks -> conflict-free fragment loads)
// ---------------------------------------------------------------------------
#define SKH 20                          // b32 units per smem row
#define STG_U32 (128*SKH)               // per-operand per-stage b32 (2560)
#define GEMM_SMEM (3 * 2 * STG_U32 * 4) // 61440 bytes

__global__ __launch_bounds__(256, 2)
void mma_gemm(const __half* __restrict__ A, const __half* __restrict__ Wp,
              const float* __restrict__ bias, const float* __restrict__ res,
              float* __restrict__ Cf, __half* __restrict__ Ch, int Nc) {
    extern __shared__ uint32_t smu[];
    const uint32_t sbase = smem_u32(smu);
    const int tid  = threadIdx.x;
    const int wid  = tid >> 5;
    const int lane = tid & 31;
    const int warp_m = wid & 1;        // 0..1
    const int warp_n = wid >> 1;       // 0..3
    const int gid = lane >> 2;         // 0..7
    const int tig = lane & 3;          // 0..3
    const int bm = blockIdx.y * 128;
    const int bn = blockIdx.x * 128;

    // cp.async: per operand 512 chunks (128 rows x 4), 2 per thread
    const int ldr = tid >> 1;          // row 0..127
    const int ldc = (tid & 1) << 1;    // chunk base 0 or 2

    auto load_stage = [&](int kt, int p) {
        const uint32_t sA = sbase + p * 2 * STG_U32 * 4;
        const uint32_t sB = sA + STG_U32 * 4;
        const __half* ga = A  + (long)(bm + ldr) * DD + kt * 32;
        const __half* gb = Wp + (long)(bn + ldr) * DD + kt * 32;
        #pragma unroll
        for (int c = 0; c < 2; c++) {
            const int ch = ldc + c;
            cp_async16(sA + (ldr * SKH + ch * 4) * 4, ga + ch * 8);
            cp_async16(sB + (ldr * SKH + ch * 4) * 4, gb + ch * 8);
        }
    };

    float acc[4][4][4];
    #pragma unroll
    for (int mt = 0; mt < 4; mt++)
        #pragma unroll
        for (int nt = 0; nt < 4; nt++)
            #pragma unroll
            for (int q = 0; q < 4; q++) acc[mt][nt][q] = 0.0f;

    const int NK = DD / 32;   // 32
    load_stage(0, 0); CP_COMMIT();
    load_stage(1, 1); CP_COMMIT();

    for (int kt = 0; kt < NK; kt++) {
        CP_WAIT1();
        __syncthreads();
        if (kt + 2 < NK) load_stage(kt + 2, (kt + 2) % 3);
        CP_COMMIT();

        const uint32_t* sA = smu + (kt % 3) * 2 * STG_U32;
        const uint32_t* sB = sA + STG_U32;
        const int mb = warp_m * 64;
        const int nb = warp_n * 32;
        #pragma unroll
        for (int ks = 0; ks < 2; ks++) {
            const int k8 = ks * 8;     // b32 offset within row
            uint32_t afr[4][4], bfr[4][2];
            #pragma unroll
            for (int mt = 0; mt < 4; mt++) {
                const int r = mb + mt * 16;
                afr[mt][0] = sA[(r + gid    ) * SKH + k8 + tig    ];
                afr[mt][1] = sA[(r + gid + 8) * SKH + k8 + tig    ];
                afr[mt][2] = sA[(r + gid    ) * SKH + k8 + tig + 4];
                afr[mt][3] = sA[(r + gid + 8) * SKH + k8 + tig + 4];
            }
            #pragma unroll
            for (int nt = 0; nt < 4; nt++) {
                const int c = nb + nt * 8;
                bfr[nt][0] = sB[(c + gid) * SKH + k8 + tig    ];
                bfr[nt][1] = sB[(c + gid) * SKH + k8 + tig + 4];
            }
            #pragma unroll
            for (int mt = 0; mt < 4; mt++)
                #pragma unroll
                for (int nt = 0; nt < 4; nt++)
                    mma_f16(acc[mt][nt], afr[mt], bfr[nt]);
        }
        __syncthreads();
    }

    // epilogue: c0,c1 -> (row, col..col+1); c2,c3 -> (row+8, col..col+1)
    #pragma unroll
    for (int mt = 0; mt < 4; mt++) {
        #pragma unroll
        for (int nt = 0; nt < 4; nt++) {
            const long row0 = bm + warp_m * 64 + mt * 16 + gid;
            const int  colg = bn + warp_n * 32 + nt * 8 + 2 * tig;
            #pragma unroll
            for (int half_i = 0; half_i < 2; half_i++) {
                const long row = row0 + half_i * 8;
                float2 v;
                v.x = acc[mt][nt][half_i * 2 + 0];
                v.y = acc[mt][nt][half_i * 2 + 1];
                const float2 bv = *(const float2*)(bias + colg);
                v.x += bv.x; v.y += bv.y;
                if (res) {
                    const float2 rv = *(const float2*)(res + row * Nc + colg);
                    v.x += rv.x; v.y += rv.y;
                }
                if (Cf) *(float2*)(Cf + row * Nc + colg) = v;
                if (Ch) {
                    __half2 hv = __floats2half2_rn(v.x, v.y);
                    *(__half2*)(Ch + row * Nc + colg) = hv;
                }
            }
        }
    }
}

// ---------------------------------------------------------------------------
// Banded attention over fused QKV (fp32, stride 3072); writes fp16 output
// ---------------------------------------------------------------------------
__global__ void attn_kernel(const float* __restrict__ QKV, __half* __restrict__ Oh) {
    const int gw = (blockIdx.x * blockDim.x + threadIdx.x) >> 5;
    const int lane = threadIdx.x & 31;
    const int h = gw & 7;
    const int s = (gw >> 3) & 255;
    const int b = gw >> 11;

    const long rb = (long)(b * TT) * 3072 + h * 128 + lane * 4;
    const float4 q4 = *(const float4*)(QKV + rb + (long)s * 3072);

    const int t0 = max(s - 3, 0);
    const int t1 = min(s + 3, TT - 1);

    float sc[7];
    float m = -1e30f;
    for (int t = t0; t <= t1; t++) {
        const float4 k4 = *(const float4*)(QKV + rb + 1024 + (long)t * 3072);
        float p = q4.x*k4.x + q4.y*k4.y + q4.z*k4.z + q4.w*k4.w;
        p += __shfl_xor_sync(0xffffffffu, p, 16);
        p += __shfl_xor_sync(0xffffffffu, p, 8);
        p += __shfl_xor_sync(0xffffffffu, p, 4);
        p += __shfl_xor_sync(0xffffffffu, p, 2);
        p += __shfl_xor_sync(0xffffffffu, p, 1);
        p *= 0.088388347648318447f;  // 1/sqrt(128)
        sc[t - t0] = p;
        m = fmaxf(m, p);
    }
    float sum = 0.0f;
    for (int t = t0; t <= t1; t++) {
        const float e = __expf(sc[t - t0] - m);
        sc[t - t0] = e;
        sum += e;
    }
    const float inv = 1.0f / sum;
    float4 o = make_float4(0.f, 0.f, 0.f, 0.f);
    for (int t = t0; t <= t1; t++) {
        const float w = sc[t - t0] * inv;
        const float4 v4 = *(const float4*)(QKV + rb + 2048 + (long)t * 3072);
        o.x += w * v4.x; o.y += w * v4.y; o.z += w * v4.z; o.w += w * v4.w;
    }
    __half2 h01 = __floats2half2_rn(o.x, o.y);
    __half2 h23 = __floats2half2_rn(o.z, o.w);
    uint2 u;
    u.x = *(uint32_t*)&h01;
    u.y = *(uint32_t*)&h23;
    *(uint2*)(Oh + (long)(b * TT + s) * 1024 + h * 128 + lane * 4) = u;
}

// ---------------------------------------------------------------------------
// BiGRU persistent kernel (reads fused gx with stride 1536); zero-fills pad
// ---------------------------------------------------------------------------
__device__ __forceinline__ float sigmoidf_(float x) { return 1.0f / (1.0f + expf(-x)); }

__global__ __launch_bounds__(256, 1)
void gru_kernel(const float* __restrict__ G,
                const float* __restrict__ Whhf, const float* __restrict__ Whhb,
                const float* __restrict__ bhhf, const float* __restrict__ bhhb,
                const int* __restrict__ seglen, float* __restrict__ out) {
    const int dir = blockIdx.x >> 6;
    const int jbase = (blockIdx.x & 63) * 4;
    const float* W  = dir ? Whhb : Whhf;
    const float* bh = dir ? bhhb : bhhf;

    __shared__ float4 sW[12][65];
    __shared__ float4 sh[64][33];
    __shared__ float  sb[12];
    __shared__ int    slen[64];

    const int tid = threadIdx.x;
    const int b  = tid >> 2;
    const int jj = tid & 3;

    for (int idx = tid; idx < 12 * 64; idx += 256) {
        const int gl = idx >> 6;
        const int k4 = idx & 63;
        const int gate = gl >> 2;
        const int ju = gl & 3;
        sW[gl][k4] = *(const float4*)(W + (gate * GH + jbase + ju) * GH + k4 * 4);
    }
    if (tid < 12) sb[tid] = bh[(tid >> 2) * GH + jbase + (tid & 3)];
    if (tid < 64) slen[tid] = seglen[tid];
    __syncthreads();

    unsigned target = 0;
    for (int t = 0; t < TT; t++) {
        const int p = t & 1;
        const float* hp = g_H + ((dir * 2 + p) * BB) * GH;
        float* hn = g_H + ((dir * 2 + (p ^ 1)) * BB) * GH;

        float accr = sb[jj], accz = sb[4 + jj], accn = sb[8 + jj];

        #pragma unroll
        for (int phase = 0; phase < 2; phase++) {
            __syncthreads();
            for (int i = 0; i < 8; i++) {
                const int idx = tid + i * 256;
                const int lb = idx >> 5;
                const int lk = idx & 31;
                sh[lb][lk] = __ldcg((const float4*)(hp + lb * GH + phase * 128) + lk);
            }
            __syncthreads();
            #pragma unroll
            for (int k4 = 0; k4 < 32; k4++) {
                const float4 hv = sh[b][k4];
                const float4 wr = sW[jj][phase * 32 + k4];
                const float4 wz = sW[4 + jj][phase * 32 + k4];
                const float4 wn = sW[8 + jj][phase * 32 + k4];
                accr += hv.x*wr.x + hv.y*wr.y + hv.z*wr.z + hv.w*wr.w;
                accz += hv.x*wz.x + hv.y*wz.y + hv.z*wz.z + hv.w*wz.w;
                accn += hv.x*wn.x + hv.y*wn.y + hv.z*wn.z + hv.w*wn.w;
            }
        }

        const int len = slen[b];
        const bool valid = (t < len);
        const int te = dir ? (len - 1 - t) : t;
        const int row = b * TT + (valid ? te : 0);
        const int jglob = jbase + jj;

        const float xr = G[(long)row * 1536 + dir * G3 + jglob];
        const float xz = G[(long)row * 1536 + dir * G3 + GH + jglob];
        const float xn = G[(long)row * 1536 + dir * G3 + 2 * GH + jglob];
        const float hpj = __ldcg(hp + b * GH + jglob);

        const float r = sigmoidf_(xr + accr);
        const float z = sigmoidf_(xz + accz);
        const float n = tanhf(xn + r * accn);
        const float hnew = valid ? ((1.0f - z) * n + z * hpj) : hpj;

        __stcg(hn + b * GH + jglob, hnew);
        if (valid)
            out[(long)(b * TT + te) * 512 + dir * GH + jglob] = hnew;
        else
            out[(long)(b * TT + t) * 512 + dir * GH + jglob] = 0.0f;  // pad region

        target += 128;
        __syncthreads();
        __threadfence();
        if (tid == 0) {
            atomicAdd(&g_bar, 1u);
            while (*(volatile unsigned*)&g_bar < target) __nanosleep(64);
            __threadfence();
        }
        __syncthreads();
    }
}

// ---------------------------------------------------------------------------
extern "C" void kernel_launch(void* const* d_in, const int* in_sizes, int n_in,
                              void* d_out, int out_size) {
    const float* seg   = (const float*)d_in[0];
    const int*   slen  = (const int*)  d_in[1];
    const float* Wq    = (const float*)d_in[2];
    const float* bq    = (const float*)d_in[3];
    const float* Wk    = (const float*)d_in[4];
    const float* bk    = (const float*)d_in[5];
    const float* Wv    = (const float*)d_in[6];
    const float* bv    = (const float*)d_in[7];
    const float* Wo    = (const float*)d_in[8];
    const float* bo    = (const float*)d_in[9];
    const float* Wihf  = (const float*)d_in[10];
    const float* Whhf  = (const float*)d_in[11];
    const float* bihf  = (const float*)d_in[12];
    const float* bhhf  = (const float*)d_in[13];
    const float* Wihb  = (const float*)d_in[14];
    const float* Whhb  = (const float*)d_in[15];
    const float* bihb  = (const float*)d_in[16];
    const float* bhhb  = (const float*)d_in[17];
    float* out = (float*)d_out;

    __half *pAh, *pAOh, *pWh;
    float *pXf, *pQKV, *pG, *pBias;
    cudaGetSymbolAddress((void**)&pAh,   g_Ah);
    cudaGetSymbolAddress((void**)&pAOh,  g_AOh);
    cudaGetSymbolAddress((void**)&pXf,   g_Xf);
    cudaGetSymbolAddress((void**)&pQKV,  g_QKV);
    cudaGetSymbolAddress((void**)&pG,    g_G);
    cudaGetSymbolAddress((void**)&pWh,   g_Wh);
    cudaGetSymbolAddress((void**)&pBias, g_bias);

    cudaFuncSetAttribute(mma_gemm, cudaFuncAttributeMaxDynamicSharedMemorySize, GEMM_SMEM);

    init_kernel<<<32, 256>>>();

    // ---- prep: fp16 A mirror + fp16 concatenated weights ----
    const int MW = 1024 * 1024;
    to_half<<<512, 256>>>(seg, pAh, (MROWS * DD) / 4);
    to_half<<<256, 256>>>(Wq,          pWh + W_QKV0,          MW / 4);
    to_half<<<256, 256>>>(Wk,          pWh + W_QKV0 + MW,     MW / 4);
    to_half<<<256, 256>>>(Wv,          pWh + W_QKV0 + 2*MW,   MW / 4);
    to_half<<<256, 256>>>(Wo,          pWh + W_O0,            MW / 4);
    to_half<<<256, 256>>>(Wq + MW,     pWh + W_QKV1,          MW / 4);
    to_half<<<256, 256>>>(Wk + MW,     pWh + W_QKV1 + MW,     MW / 4);
    to_half<<<256, 256>>>(Wv + MW,     pWh + W_QKV1 + 2*MW,   MW / 4);
    to_half<<<256, 256>>>(Wo + MW,     pWh + W_O1,            MW / 4);
    to_half<<<256, 256>>>(Wihf,        pWh + W_GRU,           (G3 * DD) / 4);
    to_half<<<256, 256>>>(Wihb,        pWh + W_GRU + G3 * DD, (G3 * DD) / 4);

    // ---- concat biases ----
    cudaMemcpyAsync(pBias + B_QKV0,          bq,        DD*4, cudaMemcpyDeviceToDevice);
    cudaMemcpyAsync(pBias + B_QKV0 + 1024,   bk,        DD*4, cudaMemcpyDeviceToDevice);
    cudaMemcpyAsync(pBias + B_QKV0 + 2048,   bv,        DD*4, cudaMemcpyDeviceToDevice);
    cudaMemcpyAsync(pBias + B_O0,            bo,        DD*4, cudaMemcpyDeviceToDevice);
    cudaMemcpyAsync(pBias + B_QKV1,          bq + DD,   DD*4, cudaMemcpyDeviceToDevice);
    cudaMemcpyAsync(pBias + B_QKV1 + 1024,   bk + DD,   DD*4, cudaMemcpyDeviceToDevice);
    cudaMemcpyAsync(pBias + B_QKV1 + 2048,   bv + DD,   DD*4, cudaMemcpyDeviceToDevice);
    cudaMemcpyAsync(pBias + B_O1,            bo + DD,   DD*4, cudaMemcpyDeviceToDevice);
    cudaMemcpyAsync(pBias + B_GRU,           bihf,      G3*4, cudaMemcpyDeviceToDevice);
    cudaMemcpyAsync(pBias + B_GRU + G3,      bihb,      G3*4, cudaMemcpyDeviceToDevice);

    const dim3 blk(256);
    const dim3 gQKV(3072 / 128, MROWS / 128);
    const dim3 gO  (1024 / 128, MROWS / 128);
    const dim3 gG_ (1536 / 128, MROWS / 128);
    const int attnBlocks = (BB * TT * HH) / 8;

    // layer 0
    mma_gemm<<<gQKV, blk, GEMM_SMEM>>>(pAh,  pWh + W_QKV0, pBias + B_QKV0, nullptr, pQKV, nullptr, 3072);
    attn_kernel<<<attnBlocks, blk>>>(pQKV, pAOh);
    mma_gemm<<<gO,   blk, GEMM_SMEM>>>(pAOh, pWh + W_O0,   pBias + B_O0,   seg,     pXf,  pAh,    1024);
    // layer 1
    mma_gemm<<<gQKV, blk, GEMM_SMEM>>>(pAh,  pWh + W_QKV1, pBias + B_QKV1, nullptr, pQKV, nullptr, 3072);
    attn_kernel<<<attnBlocks, blk>>>(pQKV, pAOh);
    mma_gemm<<<gO,   blk, GEMM_SMEM>>>(pAOh, pWh + W_O1,   pBias + B_O1,   pXf,     nullptr, pAh,  1024);
    // GRU input projections (fused fwd|bwd)
    mma_gemm<<<gG_,  blk, GEMM_SMEM>>>(pAh,  pWh + W_GRU,  pBias + B_GRU,  nullptr, pG,   nullptr, 1536);

    // BiGRU recurrence
    gru_kernel<<<128, 256>>>(pG, Whhf, Whhb, bhhf, bhhb, slen, out);
}

// round 8
// speedup vs baseline: 3.8002x; 1.6149x over previous
#include <cuda_runtime.h>
#include <cuda_fp16.h>
#include <math.h>
#include <stdint.h>

#define BB 64
#define TT 256
#define DD 1024
#define HH 8
#define GH 256
#define G3 768
#define MROWS (BB*TT)   // 16384

// ---------------- scratch (device globals; allocation forbidden) -----------
__device__ __align__(16) __half g_Ah [MROWS*DD];   // fp16 A mirror (seg_h / X_h)
__device__ __align__(16) __half g_AOh[MROWS*DD];   // fp16 attention output
__device__ __align__(16) float  g_Xf [MROWS*DD];   // fp32 X after layer0
__device__ __align__(16) __half g_QKVh[MROWS*3072];// fused QKV output (fp16)
__device__ __align__(16) float  g_G  [MROWS*1536]; // fused GRU gx (fwd|bwd), fp32
__device__ __align__(16) __half g_Wh [9961472];    // fp16 concat weights
__device__ __align__(16) float  g_bias[9728];      // concat biases (fp32)
__device__ __align__(16) __half g_Hh [2*2*BB*GH];  // fp16 h exchange [dir][parity][b][GH]
__device__ unsigned g_bar;

// Weight region offsets (elements)
#define W_QKV0 0
#define W_O0   3145728
#define W_QKV1 4194304
#define W_O1   7340032
#define W_GRU  8388608
// Bias offsets
#define B_QKV0 0
#define B_O0   3072
#define B_QKV1 4096
#define B_O1   7168
#define B_GRU  8192

// ---------------------------------------------------------------------------
__device__ __forceinline__ uint32_t smem_u32(const void* p) {
    uint32_t a;
    asm("{ .reg .u64 t; cvta.to.shared.u64 t, %1; cvt.u32.u64 %0, t; }" : "=r"(a) : "l"(p));
    return a;
}
__device__ __forceinline__ void cp_async16(uint32_t dst_smem, const void* src) {
    asm volatile("cp.async.cg.shared.global [%0], [%1], 16;" :: "r"(dst_smem), "l"(src));
}
#define CP_COMMIT() asm volatile("cp.async.commit_group;" ::: "memory")
#define CP_WAIT1()  asm volatile("cp.async.wait_group 1;" ::: "memory")

#define LDSM4(r0, r1, r2, r3, addr) \
    asm volatile("ldmatrix.sync.aligned.m8n8.x4.shared.b16 {%0,%1,%2,%3}, [%4];" \
        : "=r"(r0), "=r"(r1), "=r"(r2), "=r"(r3) : "r"(addr))

__device__ __forceinline__ void mma_f16(float* d, const uint32_t* a, const uint32_t* b) {
    asm volatile(
        "mma.sync.aligned.m16n8k16.row.col.f32.f16.f16.f32 "
        "{%0,%1,%2,%3}, {%4,%5,%6,%7}, {%8,%9}, {%0,%1,%2,%3};"
        : "+f"(d[0]), "+f"(d[1]), "+f"(d[2]), "+f"(d[3])
        : "r"(a[0]), "r"(a[1]), "r"(a[2]), "r"(a[3]), "r"(b[0]), "r"(b[1]));
}

// ---------------------------------------------------------------------------
// init: zero fp16 h parity-0 (both dirs) + barrier
// ---------------------------------------------------------------------------
__global__ void init_kernel() {
    int i = blockIdx.x * blockDim.x + threadIdx.x;
    int stride = gridDim.x * blockDim.x;
    // parity0 slices: [dir][0][.][.] -> half offsets 0 and 2*BB*GH
    for (int k = i; k < BB*GH/2; k += stride) {
        ((uint32_t*)g_Hh)[k] = 0u;                       // dir0 parity0
        ((uint32_t*)(g_Hh + 2*BB*GH))[k] = 0u;           // dir1 parity0
    }
    if (i == 0) g_bar = 0u;
}

__global__ void to_half(const float* __restrict__ src, __half* __restrict__ dst, int n4) {
    int i = blockIdx.x * blockDim.x + threadIdx.x;
    int stride = gridDim.x * blockDim.x;
    for (int k = i; k < n4; k += stride) {
        float4 v = ((const float4*)src)[k];
        __half2 h01 = __floats2half2_rn(v.x, v.y);
        __half2 h23 = __floats2half2_rn(v.z, v.w);
        uint2 u;
        u.x = *(uint32_t*)&h01;
        u.y = *(uint32_t*)&h23;
        ((uint2*)dst)[k] = u;
    }
}

// ---------------------------------------------------------------------------
// fp16 mma GEMM with ldmatrix fragments: C = A[M,1024] @ W[Nc,1024]^T + bias
// BM=128, BN=128, BK=32, 8 warps (2x4), warp tile 64x32, 3-stage cp.async
// ---------------------------------------------------------------------------
#define SKH 20                          // b32 units per smem row (80B, 16B-mult)
#define STG_U32 (128*SKH)
#define GEMM_SMEM (3 * 2 * STG_U32 * 4) // 61440 bytes

__global__ __launch_bounds__(256, 2)
void mma_gemm(const __half* __restrict__ A, const __half* __restrict__ Wp,
              const float* __restrict__ bias, const float* __restrict__ res,
              float* __restrict__ Cf, __half* __restrict__ Ch, int Nc) {
    extern __shared__ uint32_t smu[];
    const uint32_t sbase = smem_u32(smu);
    const int tid  = threadIdx.x;
    const int wid  = tid >> 5;
    const int lane = tid & 31;
    const int warp_m = wid & 1;
    const int warp_n = wid >> 1;
    const int gid = lane >> 2;
    const int tig = lane & 3;
    const int bm = blockIdx.y * 128;
    const int bn = blockIdx.x * 128;

    const int ldr = tid >> 1;
    const int ldc = (tid & 1) << 1;

    auto load_stage = [&](int kt, int p) {
        const uint32_t sA = sbase + p * 2 * STG_U32 * 4;
        const uint32_t sB = sA + STG_U32 * 4;
        const __half* ga = A  + (long)(bm + ldr) * DD + kt * 32;
        const __half* gb = Wp + (long)(bn + ldr) * DD + kt * 32;
        #pragma unroll
        for (int c = 0; c < 2; c++) {
            const int ch = ldc + c;
            cp_async16(sA + (ldr * SKH + ch * 4) * 4, ga + ch * 8);
            cp_async16(sB + (ldr * SKH + ch * 4) * 4, gb + ch * 8);
        }
    };

    float acc[4][4][4];
    #pragma unroll
    for (int mt = 0; mt < 4; mt++)
        #pragma unroll
        for (int nt = 0; nt < 4; nt++)
            #pragma unroll
            for (int q = 0; q < 4; q++) acc[mt][nt][q] = 0.0f;

    // ldmatrix per-lane offsets (bytes)
    const uint32_t a_loff = ((lane & 15) * SKH + (lane >> 4) * 4) * 4;
    const uint32_t b_loff = (((lane & 7) + (lane >> 4) * 8) * SKH + ((lane >> 3) & 1) * 4) * 4;

    const int NK = DD / 32;   // 32
    load_stage(0, 0); CP_COMMIT();
    load_stage(1, 1); CP_COMMIT();

    for (int kt = 0; kt < NK; kt++) {
        CP_WAIT1();
        __syncthreads();
        if (kt + 2 < NK) load_stage(kt + 2, (kt + 2) % 3);
        CP_COMMIT();

        const uint32_t sAb = sbase + (kt % 3) * 2 * STG_U32 * 4;
        const uint32_t sBb = sAb + STG_U32 * 4;
        const int mb = warp_m * 64;
        const int nb = warp_n * 32;
        #pragma unroll
        for (int ks = 0; ks < 2; ks++) {
            uint32_t afr[4][4], bfr[4][2];
            #pragma unroll
            for (int mt = 0; mt < 4; mt++) {
                const uint32_t ad = sAb + a_loff + ((mb + mt * 16) * SKH + ks * 8) * 4;
                LDSM4(afr[mt][0], afr[mt][1], afr[mt][2], afr[mt][3], ad);
            }
            #pragma unroll
            for (int np = 0; np < 2; np++) {
                const uint32_t bd = sBb + b_loff + ((nb + np * 16) * SKH + ks * 8) * 4;
                LDSM4(bfr[2*np][0], bfr[2*np][1], bfr[2*np+1][0], bfr[2*np+1][1], bd);
            }
            #pragma unroll
            for (int mt = 0; mt < 4; mt++)
                #pragma unroll
                for (int nt = 0; nt < 4; nt++)
                    mma_f16(acc[mt][nt], afr[mt], bfr[nt]);
        }
        __syncthreads();
    }

    // epilogue
    #pragma unroll
    for (int mt = 0; mt < 4; mt++) {
        #pragma unroll
        for (int nt = 0; nt < 4; nt++) {
            const long row0 = bm + warp_m * 64 + mt * 16 + gid;
            const int  colg = bn + warp_n * 32 + nt * 8 + 2 * tig;
            #pragma unroll
            for (int hf = 0; hf < 2; hf++) {
                const long row = row0 + hf * 8;
                float2 v;
                v.x = acc[mt][nt][hf * 2 + 0];
                v.y = acc[mt][nt][hf * 2 + 1];
                const float2 bv = *(const float2*)(bias + colg);
                v.x += bv.x; v.y += bv.y;
                if (res) {
                    const float2 rv = *(const float2*)(res + row * Nc + colg);
                    v.x += rv.x; v.y += rv.y;
                }
                if (Cf) *(float2*)(Cf + row * Nc + colg) = v;
                if (Ch) {
                    __half2 hv = __floats2half2_rn(v.x, v.y);
                    *(__half2*)(Ch + row * Nc + colg) = hv;
                }
            }
        }
    }
}

// ---------------------------------------------------------------------------
// Banded attention over fused fp16 QKV (stride 3072); writes fp16 output
// ---------------------------------------------------------------------------
__device__ __forceinline__ float4 ld_h4(const __half* p) {
    const uint2 u = *(const uint2*)p;
    const __half2* h = (const __half2*)&u;
    const float2 f01 = __half22float2(h[0]);
    const float2 f23 = __half22float2(h[1]);
    return make_float4(f01.x, f01.y, f23.x, f23.y);
}

__global__ void attn_kernel(const __half* __restrict__ QKV, __half* __restrict__ Oh) {
    const int gw = (blockIdx.x * blockDim.x + threadIdx.x) >> 5;
    const int lane = threadIdx.x & 31;
    const int h = gw & 7;
    const int s = (gw >> 3) & 255;
    const int b = gw >> 11;

    const long rb = (long)(b * TT) * 3072 + h * 128 + lane * 4;
    const float4 q4 = ld_h4(QKV + rb + (long)s * 3072);

    const int t0 = max(s - 3, 0);
    const int t1 = min(s + 3, TT - 1);

    float sc[7];
    float m = -1e30f;
    for (int t = t0; t <= t1; t++) {
        const float4 k4 = ld_h4(QKV + rb + 1024 + (long)t * 3072);
        float p = q4.x*k4.x + q4.y*k4.y + q4.z*k4.z + q4.w*k4.w;
        p += __shfl_xor_sync(0xffffffffu, p, 16);
        p += __shfl_xor_sync(0xffffffffu, p, 8);
        p += __shfl_xor_sync(0xffffffffu, p, 4);
        p += __shfl_xor_sync(0xffffffffu, p, 2);
        p += __shfl_xor_sync(0xffffffffu, p, 1);
        p *= 0.088388347648318447f;  // 1/sqrt(128)
        sc[t - t0] = p;
        m = fmaxf(m, p);
    }
    float sum = 0.0f;
    for (int t = t0; t <= t1; t++) {
        const float e = __expf(sc[t - t0] - m);
        sc[t - t0] = e;
        sum += e;
    }
    const float inv = 1.0f / sum;
    float4 o = make_float4(0.f, 0.f, 0.f, 0.f);
    for (int t = t0; t <= t1; t++) {
        const float w = sc[t - t0] * inv;
        const float4 v4 = ld_h4(QKV + rb + 2048 + (long)t * 3072);
        o.x += w * v4.x; o.y += w * v4.y; o.z += w * v4.z; o.w += w * v4.w;
    }
    __half2 h01 = __floats2half2_rn(o.x, o.y);
    __half2 h23 = __floats2half2_rn(o.z, o.w);
    uint2 u;
    u.x = *(uint32_t*)&h01;
    u.y = *(uint32_t*)&h23;
    *(uint2*)(Oh + (long)(b * TT + s) * 1024 + h * 128 + lane * 4) = u;
}

// ---------------------------------------------------------------------------
// BiGRU recurrence on tensor cores. 64 blocks x 512 thr (32 blocks/dir,
// 8 hidden units each). W_hh as persistent register b-fragments; h exchanged
// fp16 via L2; fp32 h carry thread-local; rel/acq grid barrier per step.
// ---------------------------------------------------------------------------
#define SKW 132   // u32 per smem row (256 halves + pad; 528B, 16B-mult)
#define GRU_SMEM ((32*SKW + 64*SKW) * 4 + 64*36*4)   // 59904 B

__device__ __forceinline__ float sigmoidf_(float x) { return 1.0f / (1.0f + expf(-x)); }

__global__ __launch_bounds__(512, 1)
void gru_kernel(const float* __restrict__ G,
                const float* __restrict__ Whhf, const float* __restrict__ Whhb,
                const float* __restrict__ bhhf, const float* __restrict__ bhhb,
                const int* __restrict__ seglen, float* __restrict__ out) {
    extern __shared__ uint32_t dsm[];
    uint32_t* sWu = dsm;                 // [32][SKW]
    uint32_t* sHu = dsm + 32 * SKW;      // [64][SKW]
    float*    sD  = (float*)(dsm + 96 * SKW);  // [64][36]

    const int tid = threadIdx.x;
    const int dir = blockIdx.x >> 5;
    const int jb  = (blockIdx.x & 31) * 8;
    const float* W  = dir ? Whhb : Whhf;
    const float* bh = dir ? bhhb : bhhf;

    const int lane = tid & 31;
    const int wrp  = tid >> 5;            // 0..15
    const int mt   = wrp & 3;
    const int nt   = wrp >> 2;            // 0..3
    const int gid  = lane >> 2;
    const int tig  = lane & 3;

    const int b  = tid >> 3;              // 0..63
    const int ju = tid & 7;               // 0..7

    const uint32_t sW_base = smem_u32(sWu);
    const uint32_t sH_base = smem_u32(sHu);

    // ---- load W_hh rows (24 real + 8 zero pad) as fp16 into sWu ----
    for (int idx = tid; idx < 32 * 128; idx += 512) {
        const int rr = idx >> 7;        // 0..31 row
        const int cu = idx & 127;       // u32 col (2 halves)
        uint32_t val = 0u;
        if (rr < 24) {
            const int gate = rr >> 3;
            const int j    = jb + (rr & 7);
            const float2 w2 = *(const float2*)(W + (gate * GH + j) * GH + cu * 2);
            __half2 h2 = __floats2half2_rn(w2.x, w2.y);
            val = *(uint32_t*)&h2;
        }
        sWu[rr * SKW + cu] = val;
    }

    const int len = seglen[b];
    const float br_ = bh[0*GH + jb + ju];
    const float bz_ = bh[1*GH + jb + ju];
    const float bn_ = bh[2*GH + jb + ju];

    __syncthreads();

    // ---- preload W b-fragments: per warp its nt rows, all 16 kt ----
    uint32_t bfr[16][2];
    {
        const uint32_t b_loff = ((nt * 8 + (lane & 7)) * SKW + ((lane >> 3) & 3) * 4) * 4;
        #pragma unroll
        for (int kp = 0; kp < 8; kp++) {
            uint32_t r0, r1, r2, r3;
            LDSM4(r0, r1, r2, r3, sW_base + b_loff + kp * 64);
            bfr[2*kp][0] = r0; bfr[2*kp][1] = r1;
            bfr[2*kp+1][0] = r2; bfr[2*kp+1][1] = r3;
        }
    }

    const uint32_t a_loff = ((lane & 15) * SKW + (lane >> 4) * 4) * 4;

    float hprev = 0.0f;
    unsigned target = 0;

    for (int t = 0; t < TT; t++) {
        const int p = t & 1;
        const __half* hp = g_Hh + ((dir * 2 + p) * BB) * GH;
        __half* hn = g_Hh + ((dir * 2 + (p ^ 1)) * BB) * GH;

        // prefetch gx for this thread's (b, unit)
        const bool valid = (t < len);
        const int te = dir ? (len - 1 - t) : t;
        const long grow = (long)(b * TT + (valid ? te : 0)) * 1536 + dir * G3 + jb + ju;
        const float xr = G[grow];
        const float xz = G[grow + GH];
        const float xn = G[grow + 2 * GH];

        // fill sHu from global fp16 h (parity p): 2048 uint4
        #pragma unroll
        for (int i = 0; i < 4; i++) {
            const int idx = tid + i * 512;
            const uint4 v = __ldcg(((const uint4*)hp) + idx);
            const int row = idx >> 5;
            const int ch  = idx & 31;
            *(uint4*)&sHu[row * SKW + ch * 4] = v;
        }
        __syncthreads();

        // mma: D[64x32] = H[64x256] @ W^T; warp owns (mt, nt)
        float dacc[4] = {0.f, 0.f, 0.f, 0.f};
        {
            const uint32_t abase = sH_base + a_loff + (mt * 16 * SKW) * 4;
            #pragma unroll
            for (int kt = 0; kt < 16; kt++) {
                uint32_t aa[4];
                LDSM4(aa[0], aa[1], aa[2], aa[3], abase + kt * 32);
                mma_f16(dacc, aa, bfr[kt]);
            }
        }
        // stage D
        {
            const int r0 = mt * 16 + gid;
            const int c0 = nt * 8 + 2 * tig;
            *(float2*)&sD[r0 * 36 + c0]       = make_float2(dacc[0], dacc[1]);
            *(float2*)&sD[(r0 + 8) * 36 + c0] = make_float2(dacc[2], dacc[3]);
        }
        __syncthreads();

        // elementwise GRU update
        const float pr = sD[b * 36 + ju]      + br_;
        const float pz = sD[b * 36 + 8 + ju]  + bz_;
        const float pn = sD[b * 36 + 16 + ju] + bn_;
        const float r = sigmoidf_(xr + pr);
        const float z = sigmoidf_(xz + pz);
        const float n = tanhf(xn + r * pn);
        const float hnew = valid ? ((1.0f - z) * n + z * hprev) : hprev;
        hprev = hnew;

        // store fp16 h for next step
        {
            __half hh = __float2half_rn(hnew);
            unsigned short us = *(unsigned short*)&hh;
            asm volatile("st.global.cg.u16 [%0], %1;"
                         :: "l"(hn + b * GH + jb + ju), "h"(us) : "memory");
        }
        // output (valid) / pad zero (invalid)
        if (valid)
            out[(long)(b * TT + te) * 512 + dir * GH + jb + ju] = hnew;
        else
            out[(long)(b * TT + t) * 512 + dir * GH + jb + ju] = 0.0f;

        // grid barrier: 64 arrivals, release/acquire
        target += 64;
        __syncthreads();
        if (tid == 0) {
            asm volatile("red.add.release.gpu.global.u32 [%0], 1;"
                         :: "l"(&g_bar) : "memory");
            unsigned v;
            do {
                asm volatile("ld.acquire.gpu.global.u32 %0, [%1];"
                             : "=r"(v) : "l"(&g_bar) : "memory");
            } while (v < target);
        }
        __syncthreads();
    }
}

// ---------------------------------------------------------------------------
extern "C" void kernel_launch(void* const* d_in, const int* in_sizes, int n_in,
                              void* d_out, int out_size) {
    const float* seg   = (const float*)d_in[0];
    const int*   slen  = (const int*)  d_in[1];
    const float* Wq    = (const float*)d_in[2];
    const float* bq    = (const float*)d_in[3];
    const float* Wk    = (const float*)d_in[4];
    const float* bk    = (const float*)d_in[5];
    const float* Wv    = (const float*)d_in[6];
    const float* bv    = (const float*)d_in[7];
    const float* Wo    = (const float*)d_in[8];
    const float* bo    = (const float*)d_in[9];
    const float* Wihf  = (const float*)d_in[10];
    const float* Whhf  = (const float*)d_in[11];
    const float* bihf  = (const float*)d_in[12];
    const float* bhhf  = (const float*)d_in[13];
    const float* Wihb  = (const float*)d_in[14];
    const float* Whhb  = (const float*)d_in[15];
    const float* bihb  = (const float*)d_in[16];
    const float* bhhb  = (const float*)d_in[17];
    float* out = (float*)d_out;

    __half *pAh, *pAOh, *pWh, *pQKVh;
    float *pXf, *pG, *pBias;
    cudaGetSymbolAddress((void**)&pAh,   g_Ah);
    cudaGetSymbolAddress((void**)&pAOh,  g_AOh);
    cudaGetSymbolAddress((void**)&pXf,   g_Xf);
    cudaGetSymbolAddress((void**)&pQKVh, g_QKVh);
    cudaGetSymbolAddress((void**)&pG,    g_G);
    cudaGetSymbolAddress((void**)&pWh,   g_Wh);
    cudaGetSymbolAddress((void**)&pBias, g_bias);

    cudaFuncSetAttribute(mma_gemm, cudaFuncAttributeMaxDynamicSharedMemorySize, GEMM_SMEM);
    cudaFuncSetAttribute(gru_kernel, cudaFuncAttributeMaxDynamicSharedMemorySize, GRU_SMEM);

    init_kernel<<<32, 256>>>();

    // ---- prep: fp16 A mirror + fp16 concatenated weights ----
    const int MW = 1024 * 1024;
    to_half<<<512, 256>>>(seg, pAh, (MROWS * DD) / 4);
    to_half<<<256, 256>>>(Wq,          pWh + W_QKV0,          MW / 4);
    to_half<<<256, 256>>>(Wk,          pWh + W_QKV0 + MW,     MW / 4);
    to_half<<<256, 256>>>(Wv,          pWh + W_QKV0 + 2*MW,   MW / 4);
    to_half<<<256, 256>>>(Wo,          pWh + W_O0,            MW / 4);
    to_half<<<256, 256>>>(Wq + MW,     pWh + W_QKV1,          MW / 4);
    to_half<<<256, 256>>>(Wk + MW,     pWh + W_QKV1 + MW,     MW / 4);
    to_half<<<256, 256>>>(Wv + MW,     pWh + W_QKV1 + 2*MW,   MW / 4);
    to_half<<<256, 256>>>(Wo + MW,     pWh + W_O1,            MW / 4);
    to_half<<<256, 256>>>(Wihf,        pWh + W_GRU,           (G3 * DD) / 4);
    to_half<<<256, 256>>>(Wihb,        pWh + W_GRU + G3 * DD, (G3 * DD) / 4);

    // ---- concat biases ----
    cudaMemcpyAsync(pBias + B_QKV0,          bq,        DD*4, cudaMemcpyDeviceToDevice);
    cudaMemcpyAsync(pBias + B_QKV0 + 1024,   bk,        DD*4, cudaMemcpyDeviceToDevice);
    cudaMemcpyAsync(pBias + B_QKV0 + 2048,   bv,        DD*4, cudaMemcpyDeviceToDevice);
    cudaMemcpyAsync(pBias + B_O0,            bo,        DD*4, cudaMemcpyDeviceToDevice);
    cudaMemcpyAsync(pBias + B_QKV1,          bq + DD,   DD*4, cudaMemcpyDeviceToDevice);
    cudaMemcpyAsync(pBias + B_QKV1 + 1024,   bk + DD,   DD*4, cudaMemcpyDeviceToDevice);
    cudaMemcpyAsync(pBias + B_QKV1 + 2048,   bv + DD,   DD*4, cudaMemcpyDeviceToDevice);
    cudaMemcpyAsync(pBias + B_O1,            bo + DD,   DD*4, cudaMemcpyDeviceToDevice);
    cudaMemcpyAsync(pBias + B_GRU,           bihf,      G3*4, cudaMemcpyDeviceToDevice);
    cudaMemcpyAsync(pBias + B_GRU + G3,      bihb,      G3*4, cudaMemcpyDeviceToDevice);

    const dim3 blk(256);
    const dim3 gQKV(3072 / 128, MROWS / 128);
    const dim3 gO  (1024 / 128, MROWS / 128);
    const dim3 gG_ (1536 / 128, MROWS / 128);
    const int attnBlocks = (BB * TT * HH) / 8;

    // layer 0
    mma_gemm<<<gQKV, blk, GEMM_SMEM>>>(pAh,  pWh + W_QKV0, pBias + B_QKV0, nullptr, nullptr, pQKVh, 3072);
    attn_kernel<<<attnBlocks, blk>>>(pQKVh, pAOh);
    mma_gemm<<<gO,   blk, GEMM_SMEM>>>(pAOh, pWh + W_O0,   pBias + B_O0,   seg,     pXf,  pAh,    1024);
    // layer 1
    mma_gemm<<<gQKV, blk, GEMM_SMEM>>>(pAh,  pWh + W_QKV1, pBias + B_QKV1, nullptr, nullptr, pQKVh, 3072);
    attn_kernel<<<attnBlocks, blk>>>(pQKVh, pAOh);
    mma_gemm<<<gO,   blk, GEMM_SMEM>>>(pAOh, pWh + W_O1,   pBias + B_O1,   pXf,     nullptr, pAh,  1024);
    // GRU input projections (fused fwd|bwd)
    mma_gemm<<<gG_,  blk, GEMM_SMEM>>>(pAh,  pWh + W_GRU,  pBias + B_GRU,  nullptr, pG,   nullptr, 1536);

    // BiGRU recurrence (tensor-core, persistent)
    gru_kernel<<<64, 512, GRU_SMEM>>>(pG, Whhf, Whhb, bhhf, bhhb, slen, out);
}